// round 6
// baseline (speedup 1.0000x reference)
#include <cuda_runtime.h>
#include <cstdint>

#define DIN 448
#define HEADS 8
#define HD 56
#define SEQ 8192
#define TOKENS 65536

// ---------------- scratch (device globals; no runtime alloc) ---------------
__device__ float E_g[DIN * DIN];
__device__ float Wc_g[DIN * DIN];
__device__ float Xc_g[(size_t)TOKENS * DIN];
__device__ float Yn_g[(size_t)TOKENS * DIN];

// ---------------- helpers --------------------------------------------------
__device__ __forceinline__ float tf32r(float f) {   // round-to-nearest tf32
    uint32_t u;
    asm("cvt.rna.tf32.f32 %0, %1;" : "=r"(u) : "f"(f));
    return __uint_as_float(u);
}
#define CP_ASYNC16(dst, src) \
    asm volatile("cp.async.cg.shared.global [%0], [%1], 16;" :: "r"(dst), "l"(src) : "memory")
#define CP_COMMIT() asm volatile("cp.async.commit_group;" ::: "memory")
#define CP_WAIT(n)  asm volatile("cp.async.wait_group %0;" :: "n"(n) : "memory")

__device__ __forceinline__ uint32_t smem_u32(const void* p) {
    uint32_t a;
    asm("{ .reg .u64 t; cvta.to.shared.u64 t, %1; cvt.u32.u64 %0, t; }"
        : "=r"(a) : "l"(p));
    return a;
}

// ---------------- fused GEMM: C[M,448] = A[M,448] * B[448,448]^T -----------
// CTA tile 64 x 448 (full width), 16 warps as 2m x 8n; warp tile 32x56
// (2 m16-tiles x 7 n8-tiles); warp n-slot == head. 3-stage cp.async pipe,
// one barrier per k-tile. SW128 swizzle + LDS.64 fragment pairs (k-relabel).
// EPI: true -> LayerNorm over permuted rows, write Yn (g1=gamma, g2=beta).
//      false -> bias add, write rows in place (g1=bias).
#define FBM 64
#define FBK 32
#define A_B (FBM * 128)                  //  8192 per stage
#define B_B (DIN * 128)                  // 57344 per stage
#define FB_OFF (3 * A_B)                 // 24576
#define FSMEM (FB_OFF + 3 * B_B)         // 196608

template<bool LN>
__global__ __launch_bounds__(512, 1) void gemm_fused(
    const float* __restrict__ Ag,   // [M, 448] tf32-rounded
    const float* __restrict__ Bg,   // [448, 448] row-major [n,k], tf32-rounded
    float* __restrict__ Og,
    const float* __restrict__ g1,
    const float* __restrict__ g2)
{
    extern __shared__ char sm[];
    const uint32_t sb = smem_u32(sm);
    const int tid  = threadIdx.x;
    const int warp = tid >> 5, lane = tid & 31;
    const int g  = lane >> 2, li = lane & 3;
    const int wm = warp >> 3, hh = warp & 7;        // m-half, head(=n-slot)
    const size_t M0 = (size_t)blockIdx.x * FBM;

    float acc[2][7][4];
    #pragma unroll
    for (int mt = 0; mt < 2; mt++)
        #pragma unroll
        for (int nt = 0; nt < 7; nt++)
            #pragma unroll
            for (int r = 0; r < 4; r++) acc[mt][nt][r] = 0.f;

    const int cr = tid >> 3, cc = tid & 7;          // copy lane: row, 16B-chunk

    uint32_t arow[2], brow[7];
    #pragma unroll
    for (int mt = 0; mt < 2; mt++) arow[mt] = (uint32_t)((wm * 32 + mt * 16 + g) * 128);
    #pragma unroll
    for (int nt = 0; nt < 7; nt++) brow[nt] = (uint32_t)((hh * 56 + nt * 8 + g) * 128);

    auto load_tile = [&](int kt, int st) {
        // A: 64 rows x 8 chunks = 512 ops (1/thread)
        CP_ASYNC16(sb + st * A_B + (uint32_t)cr * 128 + ((uint32_t)((cc ^ (cr & 7)) << 4)),
                   Ag + (M0 + cr) * DIN + (size_t)kt * FBK + cc * 4);
        // B: 448 rows x 8 chunks = 3584 ops (7/thread)
        const float* bs0 = Bg + (size_t)kt * FBK;
        const uint32_t bb = sb + FB_OFF + st * B_B;
        #pragma unroll
        for (int j = 0; j < 7; j++) {
            int rb = cr + 64 * j;
            CP_ASYNC16(bb + (uint32_t)rb * 128 + ((uint32_t)((cc ^ (rb & 7)) << 4)),
                       bs0 + (size_t)rb * DIN + cc * 4);
        }
    };

    const int NT = DIN / FBK;   // 14
    load_tile(0, 0); CP_COMMIT();
    load_tile(1, 1); CP_COMMIT();

    for (int kt = 0; kt < NT; kt++) {
        if (kt < NT - 1) { CP_WAIT(1); } else { CP_WAIT(0); }
        __syncthreads();   // tile kt visible; all warps done with kt-1 -> stage (kt+2)%3 free
        if (kt + 2 < NT) { load_tile(kt + 2, (kt + 2) % 3); CP_COMMIT(); }

        const int st = kt % 3;
        const char* sa  = sm + st * A_B;
        const char* sbp = sm + FB_OFF + st * B_B;

        #pragma unroll
        for (int kk = 0; kk < 4; kk++) {
            const uint32_t sw = (uint32_t)((((2 * kk + (li >> 1)) ^ g) << 4) | ((li & 1) << 3));
            float2 a0[2], a1[2], bv[7];
            #pragma unroll
            for (int mt = 0; mt < 2; mt++) {
                a0[mt] = *(const float2*)(sa + arow[mt] + sw);
                a1[mt] = *(const float2*)(sa + arow[mt] + 1024 + sw);
            }
            #pragma unroll
            for (int nt = 0; nt < 7; nt++)
                bv[nt] = *(const float2*)(sbp + brow[nt] + sw);

            #pragma unroll
            for (int mt = 0; mt < 2; mt++)
                #pragma unroll
                for (int nt = 0; nt < 7; nt++) {
                    asm volatile(
                        "mma.sync.aligned.m16n8k8.row.col.f32.tf32.tf32.f32 "
                        "{%0,%1,%2,%3}, {%4,%5,%6,%7}, {%8,%9}, {%0,%1,%2,%3};\n"
                        : "+f"(acc[mt][nt][0]), "+f"(acc[mt][nt][1]),
                          "+f"(acc[mt][nt][2]), "+f"(acc[mt][nt][3])
                        : "r"(__float_as_uint(a0[mt].x)), "r"(__float_as_uint(a1[mt].x)),
                          "r"(__float_as_uint(a0[mt].y)), "r"(__float_as_uint(a1[mt].y)),
                          "r"(__float_as_uint(bv[nt].x)), "r"(__float_as_uint(bv[nt].y)));
                }
        }
    }

    if (LN) {
        // -------- LayerNorm over permuted rows, write to Yn -----------------
        // perm row R=(b,h,q): channel c = r*56+d <- Y[token 8q+r, h*56+d].
        // This warp (wm,hh) owns q-groups j=0..3 (q = qb + wm*4 + j), head hh,
        // rows-in-group r == g, channels c = g*56 + nt*8 + 2li (same for all j).
        const int b_ = (int)(M0 >> 13);
        const int qb = (int)((M0 & 8191) >> 3);
        float gam[7][2], bet[7][2];
        #pragma unroll
        for (int nt = 0; nt < 7; nt++) {
            int c = g * 56 + nt * 8 + 2 * li;
            gam[nt][0] = g1[c]; gam[nt][1] = g1[c + 1];
            bet[nt][0] = g2[c]; bet[nt][1] = g2[c + 1];
        }
        #pragma unroll
        for (int j = 0; j < 4; j++) {
            const int mt = j >> 1, lo = (j & 1) * 2;
            float s = 0.f;
            #pragma unroll
            for (int nt = 0; nt < 7; nt++) s += acc[mt][nt][lo] + acc[mt][nt][lo + 1];
            #pragma unroll
            for (int o = 16; o > 0; o >>= 1) s += __shfl_xor_sync(0xffffffffu, s, o);
            const float mu = s * (1.f / 448.f);

            float vs = 0.f;
            #pragma unroll
            for (int nt = 0; nt < 7; nt++) {
                float d0 = acc[mt][nt][lo] - mu, d1 = acc[mt][nt][lo + 1] - mu;
                vs += d0 * d0 + d1 * d1;
            }
            #pragma unroll
            for (int o = 16; o > 0; o >>= 1) vs += __shfl_xor_sync(0xffffffffu, vs, o);
            const float rsig = rsqrtf(vs * (1.f / 448.f) + 1e-5f);

            const size_t R = (size_t)(b_ * SEQ + hh * 1024 + qb + wm * 4 + j);
            float* op = Og + R * DIN + g * 56 + 2 * li;
            #pragma unroll
            for (int nt = 0; nt < 7; nt++) {
                float2 v;
                v.x = tf32r((acc[mt][nt][lo]     - mu) * rsig * gam[nt][0] + bet[nt][0]);
                v.y = tf32r((acc[mt][nt][lo + 1] - mu) * rsig * gam[nt][1] + bet[nt][1]);
                *(float2*)(op + nt * 8) = v;
            }
        }
    } else {
        // -------- plain bias epilogue --------------------------------------
        float bb0[7][2];
        #pragma unroll
        for (int nt = 0; nt < 7; nt++) {
            int c = hh * 56 + nt * 8 + 2 * li;
            bb0[nt][0] = g1[c]; bb0[nt][1] = g1[c + 1];
        }
        #pragma unroll
        for (int mt = 0; mt < 2; mt++) {
            const size_t r0 = M0 + wm * 32 + mt * 16 + g;
            #pragma unroll
            for (int nt = 0; nt < 7; nt++) {
                const int c = hh * 56 + nt * 8 + 2 * li;
                *(float2*)&Og[r0 * DIN + c] =
                    make_float2(acc[mt][nt][0] + bb0[nt][0], acc[mt][nt][1] + bb0[nt][1]);
                *(float2*)&Og[(r0 + 8) * DIN + c] =
                    make_float2(acc[mt][nt][2] + bb0[nt][0], acc[mt][nt][3] + bb0[nt][1]);
            }
        }
    }
}

// ---------------- tf32 rounding pass ---------------------------------------
__global__ void conv_tf32(const float4* __restrict__ src, float4* __restrict__ dst, int n4) {
    int i = blockIdx.x * blockDim.x + threadIdx.x;
    if (i < n4) {
        float4 v = src[i];
        dst[i] = make_float4(tf32r(v.x), tf32r(v.y), tf32r(v.z), tf32r(v.w));
    }
}

// ---------------- E_h = C_h * M^T * A_h^T * B_h ----------------------------
// G = suffix-sum_e(A); F = C * G^T; E = F * B.  grid (8 heads, 8 o-chunks)
__global__ void computeE_k(const float* __restrict__ A, const float* __restrict__ B,
                           const float* __restrict__ C) {
    __shared__ float G[HD * HD], Cs[HD * HD], F[7 * HD];
    const int h = blockIdx.x, oc = blockIdx.y;
    const int tid = threadIdx.x;     // 448 threads
    for (int i = tid; i < HD * HD; i += 448) {
        G[i]  = A[h * HD * HD + i];
        Cs[i] = C[h * HD * HD + i];
    }
    __syncthreads();
    if (tid < HD) {
        #pragma unroll
        for (int e = HD - 2; e >= 0; e--) G[tid * HD + e] += G[tid * HD + e + 1];
    }
    __syncthreads();
    if (tid < 7 * HD) {
        int ol = tid / HD, d = tid % HD;
        float s = 0.f;
        #pragma unroll
        for (int e = 0; e < HD; e++) s += Cs[(oc * 7 + ol) * HD + e] * G[d * HD + e];
        F[ol * HD + d] = s;
    }
    __syncthreads();
    const int i = tid;
    float acc[7] = {0, 0, 0, 0, 0, 0, 0};
    for (int d = 0; d < HD; d++) {
        float b = B[(size_t)(h * HD + d) * DIN + i];
        #pragma unroll
        for (int ol = 0; ol < 7; ol++) acc[ol] += F[ol * HD + d] * b;
    }
    #pragma unroll
    for (int ol = 0; ol < 7; ol++)
        E_g[(size_t)(h * HD + oc * 7 + ol) * DIN + i] = tf32r(acc[ol]);
}

// ---------------------------------------------------------------------------
extern "C" void kernel_launch(void* const* d_in, const int* in_sizes, int n_in,
                              void* d_out, int out_size) {
    const float* x     = (const float*)d_in[0];
    const float* A     = (const float*)d_in[1];
    const float* B     = (const float*)d_in[2];
    const float* C     = (const float*)d_in[3];
    const float* gamma = (const float*)d_in[4];
    const float* beta  = (const float*)d_in[5];
    const float* W     = (const float*)d_in[6];
    const float* bias  = (const float*)d_in[7];
    float* out = (float*)d_out;

    float *E_p, *Wc_p, *Xc_p, *Yn_p;
    cudaGetSymbolAddress((void**)&E_p,  E_g);
    cudaGetSymbolAddress((void**)&Wc_p, Wc_g);
    cudaGetSymbolAddress((void**)&Xc_p, Xc_g);
    cudaGetSymbolAddress((void**)&Yn_p, Yn_g);

    cudaFuncSetAttribute(gemm_fused<true>,
                         cudaFuncAttributeMaxDynamicSharedMemorySize, FSMEM);
    cudaFuncSetAttribute(gemm_fused<false>,
                         cudaFuncAttributeMaxDynamicSharedMemorySize, FSMEM);

    conv_tf32<<<28672, 256>>>((const float4*)x, (float4*)Xc_p, 7340032);
    conv_tf32<<<196,   256>>>((const float4*)W, (float4*)Wc_p, 50176);
    computeE_k<<<dim3(HEADS, 8), DIN>>>(A, B, C);

    // GEMM1 + LayerNorm + permutation fused -> Yn
    gemm_fused<true><<<TOKENS / FBM, 512, FSMEM>>>(Xc_p, E_p, Yn_p, gamma, beta);
    // GEMM2 + bias -> out
    gemm_fused<false><<<TOKENS / FBM, 512, FSMEM>>>(Yn_p, Wc_p, out, bias, nullptr);
}

// round 7
// speedup vs baseline: 1.7780x; 1.7780x over previous
#include <cuda_runtime.h>
#include <cuda_fp16.h>
#include <cstdint>

#define DIN 448
#define HEADS 8
#define HD 56
#define SEQ 8192
#define TOKENS 65536

// ---------------- scratch (device globals; no runtime alloc) ---------------
__device__ __half Eh_g[DIN * DIN];
__device__ __half Wh_g[DIN * DIN];
__device__ __half Xh_g[(size_t)TOKENS * DIN];
__device__ float  Yg_g[(size_t)TOKENS * DIN];
__device__ __half Yn_g[(size_t)TOKENS * DIN];

// ---------------- helpers --------------------------------------------------
#define CP_ASYNC16(dst, src) \
    asm volatile("cp.async.cg.shared.global [%0], [%1], 16;" :: "r"(dst), "l"(src) : "memory")
#define CP_COMMIT() asm volatile("cp.async.commit_group;" ::: "memory")
#define CP_WAIT(n)  asm volatile("cp.async.wait_group %0;" :: "n"(n) : "memory")

__device__ __forceinline__ uint32_t smem_u32(const void* p) {
    uint32_t a;
    asm("{ .reg .u64 t; cvta.to.shared.u64 t, %1; cvt.u32.u64 %0, t; }"
        : "=r"(a) : "l"(p));
    return a;
}

// ---------------- GEMM: C[M,448] = A[M,448] * B[448,448]^T  (fp16 in, f32 out)
// Block 256x64, 4 warps, warp tile 64x64 (4 m16 x 8 n8), m16n8k16 HMMA.
// BK=64 halves = 128B/row, SW128 swizzle. k-relabel: hw slots
// {2li,2li+1,2li+8,2li+9} -> phys {4li..4li+3}; one LDS.64 = (a0,a2) etc.
// 2-stage cp.async, 2 CTAs/SM.
#define GBM 256
#define GBN 64
#define GBK 64
#define A_BYTES (GBM * 128)                 // 32768 per stage
#define B_BYTES (GBN * 128)                 // 8192 per stage
#define SB_OFF  (2 * A_BYTES)               // 65536
#define GSMEM   (SB_OFF + 2 * B_BYTES)      // 81920

__global__ __launch_bounds__(128, 2) void gemm_f16(
    const __half* __restrict__ Ag,   // [M, 448]
    const __half* __restrict__ Bg,   // [448, 448] row-major [n,k]
    float* __restrict__ Cg,          // [M, 448] f32
    const float* __restrict__ bias)  // nullable
{
    extern __shared__ char sm[];
    const uint32_t sb = smem_u32(sm);
    const int tid  = threadIdx.x;
    const int warp = tid >> 5, lane = tid & 31;
    const int g  = lane >> 2, li = lane & 3;
    const size_t M0 = (size_t)blockIdx.y * GBM;
    const int    N0 = blockIdx.x * GBN;

    float acc[4][8][4];
    #pragma unroll
    for (int mt = 0; mt < 4; mt++)
        #pragma unroll
        for (int nt = 0; nt < 8; nt++)
            #pragma unroll
            for (int r = 0; r < 4; r++) acc[mt][nt][r] = 0.f;

    const int cr = tid >> 3, cc = tid & 7;        // copy: row lane [0,16), 16B chunk

    uint32_t arow[4], brow[8];
    #pragma unroll
    for (int mt = 0; mt < 4; mt++) arow[mt] = (uint32_t)((warp * 64 + mt * 16 + g) * 128);
    #pragma unroll
    for (int nt = 0; nt < 8; nt++) brow[nt] = (uint32_t)((nt * 8 + g) * 128);

    const int NT = DIN / GBK;   // 7

    auto load_tile = [&](int kt, int st) {
        const __half* asrc = Ag + M0 * DIN + (size_t)kt * GBK;
        const uint32_t ab = sb + st * A_BYTES;
        #pragma unroll
        for (int j = 0; j < 16; j++) {            // 256 rows x 8 chunks / 128 thr
            int r = cr + 16 * j;
            CP_ASYNC16(ab + (uint32_t)r * 128 + ((uint32_t)((cc ^ (r & 7)) << 4)),
                       asrc + (size_t)r * DIN + cc * 8);
        }
        const __half* bsrc = Bg + (size_t)N0 * DIN + (size_t)kt * GBK;
        const uint32_t bb = sb + SB_OFF + st * B_BYTES;
        #pragma unroll
        for (int j = 0; j < 4; j++) {             // 64 rows x 8 chunks / 128 thr
            int r = cr + 16 * j;
            CP_ASYNC16(bb + (uint32_t)r * 128 + ((uint32_t)((cc ^ (r & 7)) << 4)),
                       bsrc + (size_t)r * DIN + cc * 8);
        }
    };

    load_tile(0, 0); CP_COMMIT();
    load_tile(1, 1); CP_COMMIT();

    for (int kt = 0; kt < NT; kt++) {
        if (kt < NT - 1) { CP_WAIT(1); } else { CP_WAIT(0); }
        __syncthreads();
        const int st = kt & 1;
        const char* sa  = sm + st * A_BYTES;
        const char* sbp = sm + SB_OFF + st * B_BYTES;

        #pragma unroll
        for (int kk = 0; kk < 4; kk++) {          // 4 x k16 per 64-deep tile
            // phys halves [kk*16 + 4li .. +3] -> byte off kk*32 + 8li
            const uint32_t sw = (uint32_t)((((2 * kk + (li >> 1)) ^ g) << 4) | ((li & 1) << 3));
            uint2 a0[4], a1[4], bv[8];
            #pragma unroll
            for (int mt = 0; mt < 4; mt++) {
                a0[mt] = *(const uint2*)(sa + arow[mt] + sw);          // row g:   (a0,a2)
                a1[mt] = *(const uint2*)(sa + arow[mt] + 1024 + sw);   // row g+8: (a1,a3)
            }
            #pragma unroll
            for (int nt = 0; nt < 8; nt++)
                bv[nt] = *(const uint2*)(sbp + brow[nt] + sw);         // (b0,b1)

            #pragma unroll
            for (int mt = 0; mt < 4; mt++)
                #pragma unroll
                for (int nt = 0; nt < 8; nt++) {
                    asm volatile(
                        "mma.sync.aligned.m16n8k16.row.col.f32.f16.f16.f32 "
                        "{%0,%1,%2,%3}, {%4,%5,%6,%7}, {%8,%9}, {%0,%1,%2,%3};\n"
                        : "+f"(acc[mt][nt][0]), "+f"(acc[mt][nt][1]),
                          "+f"(acc[mt][nt][2]), "+f"(acc[mt][nt][3])
                        : "r"(a0[mt].x), "r"(a1[mt].x), "r"(a0[mt].y), "r"(a1[mt].y),
                          "r"(bv[nt].x), "r"(bv[nt].y));
                }
        }

        if (kt + 2 < NT) {
            __syncthreads();                      // all warps done reading stage st
            load_tile(kt + 2, st);
            CP_COMMIT();
        }
    }

    // ---- epilogue: f32 store (+bias) ----
    #pragma unroll
    for (int mt = 0; mt < 4; mt++) {
        const size_t r0 = M0 + warp * 64 + mt * 16 + g;
        #pragma unroll
        for (int nt = 0; nt < 8; nt++) {
            const int c0 = N0 + nt * 8 + 2 * li;
            float b0 = 0.f, b1 = 0.f;
            if (bias) { b0 = bias[c0]; b1 = bias[c0 + 1]; }
            *(float2*)&Cg[r0 * DIN + c0] =
                make_float2(acc[mt][nt][0] + b0, acc[mt][nt][1] + b1);
            *(float2*)&Cg[(r0 + 8) * DIN + c0] =
                make_float2(acc[mt][nt][2] + b0, acc[mt][nt][3] + b1);
        }
    }
}

// ---------------- f32 -> fp16 conversion pass ------------------------------
__global__ void conv_h(const float4* __restrict__ src, __half2* __restrict__ dst, int n4) {
    int i = blockIdx.x * blockDim.x + threadIdx.x;
    if (i < n4) {
        float4 v = src[i];
        dst[2 * i]     = __floats2half2_rn(v.x, v.y);
        dst[2 * i + 1] = __floats2half2_rn(v.z, v.w);
    }
}

// ---------------- E_h = C_h * M^T * A_h^T * B_h  (-> fp16) -----------------
// G = suffix-sum_e(A); F = C * G^T; E = F * B.  grid (8 heads, 8 o-chunks)
__global__ void computeE_k(const float* __restrict__ A, const float* __restrict__ B,
                           const float* __restrict__ C) {
    __shared__ float G[HD * HD], Cs[HD * HD], F[7 * HD];
    const int h = blockIdx.x, oc = blockIdx.y;
    const int tid = threadIdx.x;     // 448 threads
    for (int i = tid; i < HD * HD; i += 448) {
        G[i]  = A[h * HD * HD + i];
        Cs[i] = C[h * HD * HD + i];
    }
    __syncthreads();
    if (tid < HD) {
        #pragma unroll
        for (int e = HD - 2; e >= 0; e--) G[tid * HD + e] += G[tid * HD + e + 1];
    }
    __syncthreads();
    if (tid < 7 * HD) {
        int ol = tid / HD, d = tid % HD;
        float s = 0.f;
        #pragma unroll
        for (int e = 0; e < HD; e++) s += Cs[(oc * 7 + ol) * HD + e] * G[d * HD + e];
        F[ol * HD + d] = s;
    }
    __syncthreads();
    const int i = tid;
    float acc[7] = {0, 0, 0, 0, 0, 0, 0};
    for (int d = 0; d < HD; d++) {
        float b = B[(size_t)(h * HD + d) * DIN + i];
        #pragma unroll
        for (int ol = 0; ol < 7; ol++) acc[ol] += F[ol * HD + d] * b;
    }
    #pragma unroll
    for (int ol = 0; ol < 7; ol++)
        Eh_g[(size_t)(h * HD + oc * 7 + ol) * DIN + i] = __float2half_rn(acc[ol]);
}

// ---------------- LayerNorm + reshape permutation (-> fp16) ----------------
__global__ void ln_permute(const float* __restrict__ Y, __half* __restrict__ Out,
                           const float* __restrict__ gamma,
                           const float* __restrict__ beta) {
    const int warp = threadIdx.x >> 5, lane = threadIdx.x & 31;
    const int R = blockIdx.x * 8 + warp;
    const int b   = R >> 13;
    const int rem = R & 8191;
    const int h   = rem >> 10;
    const int q   = rem & 1023;

    float v[14];
    #pragma unroll
    for (int j = 0; j < 14; j++) {
        int c = lane + 32 * j;
        int r = c / 56, d = c - r * 56;
        v[j] = Y[(size_t)(b * SEQ + 8 * q + r) * DIN + h * HD + d];
    }
    float s = 0.f;
    #pragma unroll
    for (int j = 0; j < 14; j++) s += v[j];
    #pragma unroll
    for (int o = 16; o > 0; o >>= 1) s += __shfl_xor_sync(0xffffffffu, s, o);
    const float mu = s * (1.f / 448.f);

    float vs = 0.f;
    #pragma unroll
    for (int j = 0; j < 14; j++) { float d2 = v[j] - mu; vs += d2 * d2; }
    #pragma unroll
    for (int o = 16; o > 0; o >>= 1) vs += __shfl_xor_sync(0xffffffffu, vs, o);
    const float rsig = rsqrtf(vs * (1.f / 448.f) + 1e-5f);

    #pragma unroll
    for (int j = 0; j < 14; j++) {
        int c = lane + 32 * j;
        Out[(size_t)R * DIN + c] = __float2half_rn((v[j] - mu) * rsig * gamma[c] + beta[c]);
    }
}

// ---------------------------------------------------------------------------
extern "C" void kernel_launch(void* const* d_in, const int* in_sizes, int n_in,
                              void* d_out, int out_size) {
    const float* x     = (const float*)d_in[0];
    const float* A     = (const float*)d_in[1];
    const float* B     = (const float*)d_in[2];
    const float* C     = (const float*)d_in[3];
    const float* gamma = (const float*)d_in[4];
    const float* beta  = (const float*)d_in[5];
    const float* W     = (const float*)d_in[6];
    const float* bias  = (const float*)d_in[7];
    float* out = (float*)d_out;

    __half *Eh_p, *Wh_p, *Xh_p, *Yn_p;
    float  *Yg_p;
    cudaGetSymbolAddress((void**)&Eh_p, Eh_g);
    cudaGetSymbolAddress((void**)&Wh_p, Wh_g);
    cudaGetSymbolAddress((void**)&Xh_p, Xh_g);
    cudaGetSymbolAddress((void**)&Yg_p, Yg_g);
    cudaGetSymbolAddress((void**)&Yn_p, Yn_g);

    cudaFuncSetAttribute(gemm_f16, cudaFuncAttributeMaxDynamicSharedMemorySize, GSMEM);

    conv_h<<<28672, 256>>>((const float4*)x, (__half2*)Xh_p, 7340032);
    conv_h<<<196,   256>>>((const float4*)W, (__half2*)Wh_p, 50176);
    computeE_k<<<dim3(HEADS, 8), DIN>>>(A, B, C);

    dim3 grid(DIN / GBN, TOKENS / GBM);   // (7, 256): N fastest for L2 reuse of A tiles
    gemm_f16<<<grid, 128, GSMEM>>>(Xh_p, Eh_p, Yg_p, nullptr);
    ln_permute<<<TOKENS / 8, 256>>>(Yg_p, Yn_p, gamma, beta);
    gemm_f16<<<grid, 128, GSMEM>>>(Yn_p, Wh_p, out, bias);
}

// round 8
// speedup vs baseline: 1.8776x; 1.0560x over previous
#include <cuda_runtime.h>
#include <cuda_fp16.h>
#include <cstdint>

#define DIN 448
#define HEADS 8
#define HD 56
#define SEQ 8192
#define TOKENS 65536

// ---------------- scratch (device globals; no runtime alloc) ---------------
__device__ __half Eh_g[DIN * DIN];
__device__ __half Wh_g[DIN * DIN];
__device__ __half Xh_g[(size_t)TOKENS * DIN];
__device__ __half Yn_g[(size_t)TOKENS * DIN];

// ---------------- helpers --------------------------------------------------
#define CP_ASYNC16(dst, src) \
    asm volatile("cp.async.cg.shared.global [%0], [%1], 16;" :: "r"(dst), "l"(src) : "memory")
#define CP_COMMIT() asm volatile("cp.async.commit_group;" ::: "memory")
#define CP_WAIT(n)  asm volatile("cp.async.wait_group %0;" :: "n"(n) : "memory")

__device__ __forceinline__ uint32_t smem_u32(const void* p) {
    uint32_t a;
    asm("{ .reg .u64 t; cvta.to.shared.u64 t, %1; cvt.u32.u64 %0, t; }"
        : "=r"(a) : "l"(p));
    return a;
}

// ---------------- GEMM: C[M,448] = A[M,448] * B[448,448]^T  (fp16, f32 acc)
// Block 256x56 (one head's columns), 4 warps, warp tile 64x56 (4 m16 x 7 n8),
// m16n8k16 HMMA. BK=64 -> 128B rows, SW128 swizzle, LDS.64 k-relabel.
// B (56x448) preloaded whole; A 2-stage cp.async; 2 CTAs/SM.
// LN=true : epilogue stages the 32 complete permuted rows through smem,
//           LayerNorms with f32 stats, writes fp16 Yn (g1=gamma, g2=beta).
// LN=false: bias epilogue, f32 store (g1=bias).
#define GBM 256
#define GBN 56
#define GBK 64
#define A_BYTES (GBM * 128)            // 32768 per stage
#define SB_OFF  (2 * A_BYTES)          // 65536
#define B_CHUNK (GBN * 128)            // 7168 per k-tile
#define NT      (DIN / GBK)            // 7
#define GSMEM   (SB_OFF + NT * B_CHUNK) // 115712

template<bool LN>
__global__ __launch_bounds__(128, 2) void gemm_f16(
    const __half* __restrict__ Ag,   // [M, 448]
    const __half* __restrict__ Bg,   // [448, 448] row-major [n,k]
    void* __restrict__ Og,           // LN: __half Yn ; else float out
    const float* __restrict__ g1,
    const float* __restrict__ g2)
{
    extern __shared__ char sm[];
    const uint32_t sb = smem_u32(sm);
    const int tid  = threadIdx.x;
    const int warp = tid >> 5, lane = tid & 31;
    const int g  = lane >> 2, li = lane & 3;
    const int hh = blockIdx.x;                    // N-block == head
    const int N0 = hh * GBN;
    const size_t M0 = (size_t)blockIdx.y * GBM;

    float acc[4][7][4];
    #pragma unroll
    for (int mt = 0; mt < 4; mt++)
        #pragma unroll
        for (int nt = 0; nt < 7; nt++)
            #pragma unroll
            for (int r = 0; r < 4; r++) acc[mt][nt][r] = 0.f;

    const int cr = tid >> 3, cc = tid & 7;        // A copy: row lane [0,16), 16B chunk

    uint32_t arow[4], brow[7];
    #pragma unroll
    for (int mt = 0; mt < 4; mt++) arow[mt] = (uint32_t)((warp * 64 + mt * 16 + g) * 128);
    #pragma unroll
    for (int nt = 0; nt < 7; nt++) brow[nt] = (uint32_t)((nt * 8 + g) * 128);

    auto load_tileA = [&](int kt, int st) {
        const __half* asrc = Ag + M0 * DIN + (size_t)kt * GBK;
        const uint32_t ab = sb + st * A_BYTES;
        #pragma unroll
        for (int j = 0; j < 16; j++) {            // 256 rows x 8 chunks / 128 thr
            int r = cr + 16 * j;
            CP_ASYNC16(ab + (uint32_t)r * 128 + ((uint32_t)((cc ^ (r & 7)) << 4)),
                       asrc + (size_t)r * DIN + cc * 8);
        }
    };

    // ---- prologue: whole B (7 k-chunks x 56 rows x 128B) + A tiles 0,1 ----
    #pragma unroll
    for (int j = 0; j < 25; j++) {                // 3136 16B ops / 128 thr
        int o = tid + 128 * j;
        if (o < NT * GBN * 8) {
            int kt = o / (GBN * 8), rem = o % (GBN * 8);
            int row = rem >> 3, c2 = rem & 7;
            CP_ASYNC16(sb + SB_OFF + kt * B_CHUNK + (uint32_t)row * 128
                           + ((uint32_t)((c2 ^ (row & 7)) << 4)),
                       Bg + (size_t)(N0 + row) * DIN + (size_t)kt * GBK + c2 * 8);
        }
    }
    load_tileA(0, 0); CP_COMMIT();                // group0 = B + A0
    load_tileA(1, 1); CP_COMMIT();                // group1 = A1

    for (int kt = 0; kt < NT; kt++) {
        if (kt < NT - 1) { CP_WAIT(1); } else { CP_WAIT(0); }
        __syncthreads();
        const char* sa  = sm + (kt & 1) * A_BYTES;
        const char* sbp = sm + SB_OFF + kt * B_CHUNK;

        #pragma unroll
        for (int kk = 0; kk < 4; kk++) {
            const uint32_t sw = (uint32_t)((((2 * kk + (li >> 1)) ^ g) << 4) | ((li & 1) << 3));
            uint2 a0[4], a1[4], bv[7];
            #pragma unroll
            for (int mt = 0; mt < 4; mt++) {
                a0[mt] = *(const uint2*)(sa + arow[mt] + sw);          // row g:   (a0,a2)
                a1[mt] = *(const uint2*)(sa + arow[mt] + 1024 + sw);   // row g+8: (a1,a3)
            }
            #pragma unroll
            for (int nt = 0; nt < 7; nt++)
                bv[nt] = *(const uint2*)(sbp + brow[nt] + sw);
            #pragma unroll
            for (int mt = 0; mt < 4; mt++)
                #pragma unroll
                for (int nt = 0; nt < 7; nt++) {
                    asm volatile(
                        "mma.sync.aligned.m16n8k16.row.col.f32.f16.f16.f32 "
                        "{%0,%1,%2,%3}, {%4,%5,%6,%7}, {%8,%9}, {%0,%1,%2,%3};\n"
                        : "+f"(acc[mt][nt][0]), "+f"(acc[mt][nt][1]),
                          "+f"(acc[mt][nt][2]), "+f"(acc[mt][nt][3])
                        : "r"(a0[mt].x), "r"(a1[mt].x), "r"(a0[mt].y), "r"(a1[mt].y),
                          "r"(bv[nt].x), "r"(bv[nt].y));
                }
        }

        if (kt + 2 < NT) {
            __syncthreads();                      // all warps done reading stage kt&1
            load_tileA(kt + 2, kt & 1);
            CP_COMMIT();
        }
    }

    if (LN) {
        // ---- stage the 32 complete permuted rows [32 x 448] f32 in smem ----
        // token t = M0 + warp*64 + mt*16 + g (+8): r = t&7 = g, q_local = warp*8+mt*2 (+1)
        // permuted col = g*56 + d,  d = nt*8 + 2li
        __syncthreads();                          // mainloop smem reads complete
        float* sp = (float*)sm;                   // 32*448*4 = 57344 <= 65536 (A area)
        #pragma unroll
        for (int mt = 0; mt < 4; mt++) {
            const int q0 = warp * 8 + mt * 2;
            #pragma unroll
            for (int nt = 0; nt < 7; nt++) {
                const int col = g * 56 + nt * 8 + 2 * li;
                *(float2*)&sp[(q0 + 0) * 448 + col] = make_float2(acc[mt][nt][0], acc[mt][nt][1]);
                *(float2*)&sp[(q0 + 1) * 448 + col] = make_float2(acc[mt][nt][2], acc[mt][nt][3]);
            }
        }
        __syncthreads();

        const int b_  = (int)(M0 >> 13);
        const int qg0 = (int)((M0 & 8191) >> 3);
        __half* Yn = (__half*)Og;
        for (int qq = 0; qq < 8; qq++) {          // warp handles 8 rows
            const int q = warp * 8 + qq;
            float2 v[7];
            #pragma unroll
            for (int j = 0; j < 7; j++)
                v[j] = *(const float2*)&sp[q * 448 + 2 * lane + 64 * j];

            float s = 0.f;
            #pragma unroll
            for (int j = 0; j < 7; j++) s += v[j].x + v[j].y;
            #pragma unroll
            for (int o = 16; o > 0; o >>= 1) s += __shfl_xor_sync(0xffffffffu, s, o);
            const float mu = s * (1.f / 448.f);

            float vs = 0.f;
            #pragma unroll
            for (int j = 0; j < 7; j++) {
                float d0 = v[j].x - mu, d1 = v[j].y - mu;
                vs += d0 * d0 + d1 * d1;
            }
            #pragma unroll
            for (int o = 16; o > 0; o >>= 1) vs += __shfl_xor_sync(0xffffffffu, vs, o);
            const float rsig = rsqrtf(vs * (1.f / 448.f) + 1e-5f);

            const size_t R = (size_t)(b_ * SEQ + hh * 1024 + qg0 + q);
            __half2* op = (__half2*)(Yn + R * DIN);
            #pragma unroll
            for (int j = 0; j < 7; j++) {
                const int c = 2 * lane + 64 * j;
                float2 gm = *(const float2*)&g1[c];
                float2 bt = *(const float2*)&g2[c];
                op[lane + 32 * j] = __floats2half2_rn(
                    (v[j].x - mu) * rsig * gm.x + bt.x,
                    (v[j].y - mu) * rsig * gm.y + bt.y);
            }
        }
    } else {
        // ---- bias epilogue, f32 store ----
        float* Cg = (float*)Og;
        #pragma unroll
        for (int mt = 0; mt < 4; mt++) {
            const size_t r0 = M0 + warp * 64 + mt * 16 + g;
            #pragma unroll
            for (int nt = 0; nt < 7; nt++) {
                const int c0 = N0 + nt * 8 + 2 * li;
                float2 bb = *(const float2*)&g1[c0];
                *(float2*)&Cg[r0 * DIN + c0] =
                    make_float2(acc[mt][nt][0] + bb.x, acc[mt][nt][1] + bb.y);
                *(float2*)&Cg[(r0 + 8) * DIN + c0] =
                    make_float2(acc[mt][nt][2] + bb.x, acc[mt][nt][3] + bb.y);
            }
        }
    }
}

// ---------------- f32 -> fp16 conversion pass ------------------------------
__global__ void conv_h(const float4* __restrict__ src, __half2* __restrict__ dst, int n4) {
    int i = blockIdx.x * blockDim.x + threadIdx.x;
    if (i < n4) {
        float4 v = src[i];
        dst[2 * i]     = __floats2half2_rn(v.x, v.y);
        dst[2 * i + 1] = __floats2half2_rn(v.z, v.w);
    }
}

// ---------------- E_h = C_h * M^T * A_h^T * B_h  (-> fp16) -----------------
__global__ void computeE_k(const float* __restrict__ A, const float* __restrict__ B,
                           const float* __restrict__ C) {
    __shared__ float G[HD * HD], Cs[HD * HD], F[7 * HD];
    const int h = blockIdx.x, oc = blockIdx.y;
    const int tid = threadIdx.x;     // 448 threads
    for (int i = tid; i < HD * HD; i += 448) {
        G[i]  = A[h * HD * HD + i];
        Cs[i] = C[h * HD * HD + i];
    }
    __syncthreads();
    if (tid < HD) {
        #pragma unroll
        for (int e = HD - 2; e >= 0; e--) G[tid * HD + e] += G[tid * HD + e + 1];
    }
    __syncthreads();
    if (tid < 7 * HD) {
        int ol = tid / HD, d = tid % HD;
        float s = 0.f;
        #pragma unroll
        for (int e = 0; e < HD; e++) s += Cs[(oc * 7 + ol) * HD + e] * G[d * HD + e];
        F[ol * HD + d] = s;
    }
    __syncthreads();
    const int i = tid;
    float acc[7] = {0, 0, 0, 0, 0, 0, 0};
    for (int d = 0; d < HD; d++) {
        float b = B[(size_t)(h * HD + d) * DIN + i];
        #pragma unroll
        for (int ol = 0; ol < 7; ol++) acc[ol] += F[ol * HD + d] * b;
    }
    #pragma unroll
    for (int ol = 0; ol < 7; ol++)
        Eh_g[(size_t)(h * HD + oc * 7 + ol) * DIN + i] = __float2half_rn(acc[ol]);
}

// ---------------------------------------------------------------------------
extern "C" void kernel_launch(void* const* d_in, const int* in_sizes, int n_in,
                              void* d_out, int out_size) {
    const float* x     = (const float*)d_in[0];
    const float* A     = (const float*)d_in[1];
    const float* B     = (const float*)d_in[2];
    const float* C     = (const float*)d_in[3];
    const float* gamma = (const float*)d_in[4];
    const float* beta  = (const float*)d_in[5];
    const float* W     = (const float*)d_in[6];
    const float* bias  = (const float*)d_in[7];
    float* out = (float*)d_out;

    __half *Eh_p, *Wh_p, *Xh_p, *Yn_p;
    cudaGetSymbolAddress((void**)&Eh_p, Eh_g);
    cudaGetSymbolAddress((void**)&Wh_p, Wh_g);
    cudaGetSymbolAddress((void**)&Xh_p, Xh_g);
    cudaGetSymbolAddress((void**)&Yn_p, Yn_g);

    cudaFuncSetAttribute(gemm_f16<true>,
                         cudaFuncAttributeMaxDynamicSharedMemorySize, GSMEM);
    cudaFuncSetAttribute(gemm_f16<false>,
                         cudaFuncAttributeMaxDynamicSharedMemorySize, GSMEM);

    conv_h<<<28672, 256>>>((const float4*)x, (__half2*)Xh_p, 7340032);
    conv_h<<<196,   256>>>((const float4*)W, (__half2*)Wh_p, 50176);
    computeE_k<<<dim3(HEADS, 8), DIN>>>(A, B, C);

    dim3 grid(HEADS, TOKENS / GBM);   // (8 heads fast, 256): x tiles L2-reused x8
    // GEMM1 + LayerNorm + permutation fused -> Yn (fp16)
    gemm_f16<true><<<grid, 128, GSMEM>>>(Xh_p, Eh_p, Yn_p, gamma, beta);
    // GEMM2 + bias -> out (f32)
    gemm_f16<false><<<grid, 128, GSMEM>>>(Yn_p, Wh_p, out, bias, nullptr);
}

// round 9
// speedup vs baseline: 2.0084x; 1.0697x over previous
#include <cuda_runtime.h>
#include <cuda_fp16.h>
#include <cstdint>

#define DIN 448
#define HEADS 8
#define HD 56
#define SEQ 8192
#define TOKENS 65536
#define NSLOT 37                      // CTAs per head; grid = 8*37 = 296 = 2/SM
#define MTILES 256                    // 65536 / 256

// ---------------- scratch (device globals; no runtime alloc) ---------------
__device__ __half Eh_g[DIN * DIN];
__device__ __half Wh_g[DIN * DIN];
__device__ __half Xh_g[(size_t)TOKENS * DIN];
__device__ __half Yn_g[(size_t)TOKENS * DIN];

// ---------------- helpers --------------------------------------------------
#define CP_ASYNC16(dst, src) \
    asm volatile("cp.async.cg.shared.global [%0], [%1], 16;" :: "r"(dst), "l"(src) : "memory")
#define CP_COMMIT() asm volatile("cp.async.commit_group;" ::: "memory")
#define CP_WAIT1()  asm volatile("cp.async.wait_group 1;" ::: "memory")
#define CP_WAIT0()  asm volatile("cp.async.wait_group 0;" ::: "memory")

__device__ __forceinline__ uint32_t smem_u32(const void* p) {
    uint32_t a;
    asm("{ .reg .u64 t; cvta.to.shared.u64 t, %1; cvt.u32.u64 %0, t; }"
        : "=r"(a) : "l"(p));
    return a;
}

// ---------------- persistent GEMM: C[M,448] = A[M,448]*B[448,448]^T --------
// CTA: one n-chunk (head) of 56 cols, 6-7 M-tiles of 256 rows. 4 warps,
// warp tile 64x56 (4 m16 x 7 n8), m16n8k16 HMMA, f32 acc. BK=64 (128B rows),
// SW128 swizzle, LDS.64 k-relabel. B (56x448) loaded once; A 2-stage cp.async
// pipelined ACROSS m-tiles. 2 CTAs/SM.
// LN=true : register-only LayerNorm epilogue -> fp16 Yn (g1=gamma, g2=beta)
// LN=false: bias epilogue -> f32 out (g1=bias)
#define GBM 256
#define GBK 64
#define A_BYTES (GBM * 128)              // 32768 per stage
#define SB_OFF  (2 * A_BYTES)            // 65536
#define B_CHUNK (HD * 128)               // 7168 per k-tile
#define NKT     (DIN / GBK)              // 7
#define GSMEM   (SB_OFF + NKT * B_CHUNK) // 115712

template<bool LN>
__global__ __launch_bounds__(128, 2) void gemm_f16(
    const __half* __restrict__ Ag,
    const __half* __restrict__ Bg,
    void* __restrict__ Og,
    const float* __restrict__ g1,
    const float* __restrict__ g2)
{
    extern __shared__ char sm[];
    const uint32_t sb = smem_u32(sm);
    const int tid  = threadIdx.x;
    const int warp = tid >> 5, lane = tid & 31;
    const int g  = lane >> 2, li = lane & 3;
    const int hh   = blockIdx.x & 7;              // n-chunk (head)
    const int slot = blockIdx.x >> 3;             // 0..36
    const int N0 = hh * HD;
    const int ntile = (slot + NSLOT * 6 < MTILES) ? 7 : 6;
    const int total = ntile * NKT;

    const int cr = tid >> 3, cc = tid & 7;

    uint32_t arow[4], brow[7];
    #pragma unroll
    for (int mt = 0; mt < 4; mt++) arow[mt] = (uint32_t)((warp * 64 + mt * 16 + g) * 128);
    #pragma unroll
    for (int nt = 0; nt < 7; nt++) brow[nt] = (uint32_t)((nt * 8 + g) * 128);

    // hoisted per-lane epilogue params
    float2 p1[7], p2[7];
    #pragma unroll
    for (int nt = 0; nt < 7; nt++) {
        if (LN) {
            const int c = g * 56 + nt * 8 + 2 * li;      // permuted channel
            p1[nt] = *(const float2*)&g1[c];
            p2[nt] = *(const float2*)&g2[c];
        } else {
            const int c = N0 + nt * 8 + 2 * li;          // plain channel
            p1[nt] = *(const float2*)&g1[c];
        }
    }

    auto load_tileA = [&](int mi, int kt, int st) {
        const __half* asrc = Ag + (size_t)mi * GBM * DIN + (size_t)kt * GBK;
        const uint32_t ab = sb + st * A_BYTES;
        #pragma unroll
        for (int j = 0; j < 16; j++) {
            int r = cr + 16 * j;
            CP_ASYNC16(ab + (uint32_t)r * 128 + ((uint32_t)((cc ^ (r & 7)) << 4)),
                       asrc + (size_t)r * DIN + cc * 8);
        }
    };

    // ---- prologue: whole B + A tiles (slot,0), (slot,1) ----
    #pragma unroll
    for (int j = 0; j < 25; j++) {                // 7*56*8 = 3136 16B ops
        int o = tid + 128 * j;
        if (o < NKT * HD * 8) {
            int kt = o / (HD * 8), rem = o % (HD * 8);
            int row = rem >> 3, c2 = rem & 7;
            CP_ASYNC16(sb + SB_OFF + kt * B_CHUNK + (uint32_t)row * 128
                           + ((uint32_t)((c2 ^ (row & 7)) << 4)),
                       Bg + (size_t)(N0 + row) * DIN + (size_t)kt * GBK + c2 * 8);
        }
    }
    load_tileA(slot, 0, 0); CP_COMMIT();
    load_tileA(slot, 1, 1); CP_COMMIT();

    float acc[4][7][4];
    #pragma unroll
    for (int mt = 0; mt < 4; mt++)
        #pragma unroll
        for (int nt = 0; nt < 7; nt++)
            #pragma unroll
            for (int r = 0; r < 4; r++) acc[mt][nt][r] = 0.f;

    int ck = 0, cmi = slot;        // consume coords
    int pk = 2, pmi = slot;        // prefetch coords (tile t+2)

    for (int t = 0; t < total; t++) {
        if (t < total - 1) { CP_WAIT1(); } else { CP_WAIT0(); }
        __syncthreads();
        const char* sa  = sm + (t & 1) * A_BYTES;
        const char* sbp = sm + SB_OFF + ck * B_CHUNK;

        #pragma unroll
        for (int kk = 0; kk < 4; kk++) {
            const uint32_t sw = (uint32_t)((((2 * kk + (li >> 1)) ^ g) << 4) | ((li & 1) << 3));
            uint2 a0[4], a1[4], bv[7];
            #pragma unroll
            for (int mt = 0; mt < 4; mt++) {
                a0[mt] = *(const uint2*)(sa + arow[mt] + sw);
                a1[mt] = *(const uint2*)(sa + arow[mt] + 1024 + sw);
            }
            #pragma unroll
            for (int nt = 0; nt < 7; nt++)
                bv[nt] = *(const uint2*)(sbp + brow[nt] + sw);
            #pragma unroll
            for (int mt = 0; mt < 4; mt++)
                #pragma unroll
                for (int nt = 0; nt < 7; nt++) {
                    asm volatile(
                        "mma.sync.aligned.m16n8k16.row.col.f32.f16.f16.f32 "
                        "{%0,%1,%2,%3}, {%4,%5,%6,%7}, {%8,%9}, {%0,%1,%2,%3};\n"
                        : "+f"(acc[mt][nt][0]), "+f"(acc[mt][nt][1]),
                          "+f"(acc[mt][nt][2]), "+f"(acc[mt][nt][3])
                        : "r"(a0[mt].x), "r"(a1[mt].x), "r"(a0[mt].y), "r"(a1[mt].y),
                          "r"(bv[nt].x), "r"(bv[nt].y));
                }
        }
        __syncthreads();                           // stage (t&1) free for reuse
        if (t + 2 < total) {
            load_tileA(pmi, pk, t & 1);
            CP_COMMIT();
            if (++pk == NKT) { pk = 0; pmi += NSLOT; }
        }

        if (ck == NKT - 1) {
            // ================= epilogue for m-tile cmi =====================
            const size_t M0 = (size_t)cmi * GBM;
            if (LN) {
                __half* Yn = (__half*)Og;
                #pragma unroll
                for (int mt = 0; mt < 4; mt++) {
                    const size_t tok0 = M0 + warp * 64 + mt * 16;   // q-group lo
                    #pragma unroll
                    for (int hf = 0; hf < 2; hf++) {                // lo, hi row
                        const int lo = hf * 2;
                        float s = 0.f;
                        #pragma unroll
                        for (int nt = 0; nt < 7; nt++)
                            s += acc[mt][nt][lo] + acc[mt][nt][lo + 1];
                        #pragma unroll
                        for (int o = 16; o > 0; o >>= 1)
                            s += __shfl_xor_sync(0xffffffffu, s, o);
                        const float mu = s * (1.f / 448.f);
                        float vs = 0.f;
                        #pragma unroll
                        for (int nt = 0; nt < 7; nt++) {
                            float d0 = acc[mt][nt][lo] - mu;
                            float d1 = acc[mt][nt][lo + 1] - mu;
                            vs += d0 * d0 + d1 * d1;
                        }
                        #pragma unroll
                        for (int o = 16; o > 0; o >>= 1)
                            vs += __shfl_xor_sync(0xffffffffu, vs, o);
                        const float rsig = rsqrtf(vs * (1.f / 448.f) + 1e-5f);

                        const size_t tok = tok0 + hf * 8;
                        const size_t R = (tok >> 13) * SEQ + (size_t)hh * 1024
                                       + ((tok & 8191) >> 3);
                        __half* op = Yn + R * DIN + g * 56 + 2 * li;
                        #pragma unroll
                        for (int nt = 0; nt < 7; nt++) {
                            *(__half2*)(op + nt * 8) = __floats2half2_rn(
                                (acc[mt][nt][lo]     - mu) * rsig * p1[nt].x + p2[nt].x,
                                (acc[mt][nt][lo + 1] - mu) * rsig * p1[nt].y + p2[nt].y);
                        }
                    }
                }
            } else {
                float* Cg = (float*)Og;
                #pragma unroll
                for (int mt = 0; mt < 4; mt++) {
                    const size_t r0 = M0 + warp * 64 + mt * 16 + g;
                    #pragma unroll
                    for (int nt = 0; nt < 7; nt++) {
                        const int c0 = N0 + nt * 8 + 2 * li;
                        *(float2*)&Cg[r0 * DIN + c0] =
                            make_float2(acc[mt][nt][0] + p1[nt].x, acc[mt][nt][1] + p1[nt].y);
                        *(float2*)&Cg[(r0 + 8) * DIN + c0] =
                            make_float2(acc[mt][nt][2] + p1[nt].x, acc[mt][nt][3] + p1[nt].y);
                    }
                }
            }
            #pragma unroll
            for (int mt = 0; mt < 4; mt++)
                #pragma unroll
                for (int nt = 0; nt < 7; nt++)
                    #pragma unroll
                    for (int r = 0; r < 4; r++) acc[mt][nt][r] = 0.f;
            ck = 0; cmi += NSLOT;
        } else {
            ck++;
        }
    }
}

// ---------------- f32 -> fp16 conversion pass ------------------------------
__global__ void conv_h(const float4* __restrict__ src, __half2* __restrict__ dst, int n4) {
    int i = blockIdx.x * blockDim.x + threadIdx.x;
    if (i < n4) {
        float4 v = src[i];
        dst[2 * i]     = __floats2half2_rn(v.x, v.y);
        dst[2 * i + 1] = __floats2half2_rn(v.z, v.w);
    }
}

// ---------------- E_h = C_h * M^T * A_h^T * B_h  (-> fp16) -----------------
__global__ void computeE_k(const float* __restrict__ A, const float* __restrict__ B,
                           const float* __restrict__ C) {
    __shared__ float G[HD * HD], Cs[HD * HD], F[7 * HD];
    const int h = blockIdx.x, oc = blockIdx.y;
    const int tid = threadIdx.x;     // 448 threads
    for (int i = tid; i < HD * HD; i += 448) {
        G[i]  = A[h * HD * HD + i];
        Cs[i] = C[h * HD * HD + i];
    }
    __syncthreads();
    if (tid < HD) {
        #pragma unroll
        for (int e = HD - 2; e >= 0; e--) G[tid * HD + e] += G[tid * HD + e + 1];
    }
    __syncthreads();
    if (tid < 7 * HD) {
        int ol = tid / HD, d = tid % HD;
        float s = 0.f;
        #pragma unroll
        for (int e = 0; e < HD; e++) s += Cs[(oc * 7 + ol) * HD + e] * G[d * HD + e];
        F[ol * HD + d] = s;
    }
    __syncthreads();
    const int i = tid;
    float acc[7] = {0, 0, 0, 0, 0, 0, 0};
    for (int d = 0; d < HD; d++) {
        float b = B[(size_t)(h * HD + d) * DIN + i];
        #pragma unroll
        for (int ol = 0; ol < 7; ol++) acc[ol] += F[ol * HD + d] * b;
    }
    #pragma unroll
    for (int ol = 0; ol < 7; ol++)
        Eh_g[(size_t)(h * HD + oc * 7 + ol) * DIN + i] = __float2half_rn(acc[ol]);
}

// ---------------------------------------------------------------------------
extern "C" void kernel_launch(void* const* d_in, const int* in_sizes, int n_in,
                              void* d_out, int out_size) {
    const float* x     = (const float*)d_in[0];
    const float* A     = (const float*)d_in[1];
    const float* B     = (const float*)d_in[2];
    const float* C     = (const float*)d_in[3];
    const float* gamma = (const float*)d_in[4];
    const float* beta  = (const float*)d_in[5];
    const float* W     = (const float*)d_in[6];
    const float* bias  = (const float*)d_in[7];
    float* out = (float*)d_out;

    __half *Eh_p, *Wh_p, *Xh_p, *Yn_p;
    cudaGetSymbolAddress((void**)&Eh_p, Eh_g);
    cudaGetSymbolAddress((void**)&Wh_p, Wh_g);
    cudaGetSymbolAddress((void**)&Xh_p, Xh_g);
    cudaGetSymbolAddress((void**)&Yn_p, Yn_g);

    cudaFuncSetAttribute(gemm_f16<true>,
                         cudaFuncAttributeMaxDynamicSharedMemorySize, GSMEM);
    cudaFuncSetAttribute(gemm_f16<false>,
                         cudaFuncAttributeMaxDynamicSharedMemorySize, GSMEM);

    conv_h<<<28672, 256>>>((const float4*)x, (__half2*)Xh_p, 7340032);
    conv_h<<<196,   256>>>((const float4*)W, (__half2*)Wh_p, 50176);
    computeE_k<<<dim3(HEADS, 8), DIN>>>(A, B, C);

    // GEMM1 + LayerNorm + permutation fused -> Yn (fp16), persistent CTAs
    gemm_f16<true><<<HEADS * NSLOT, 128, GSMEM>>>(Xh_p, Eh_p, Yn_p, gamma, beta);
    // GEMM2 + bias -> out (f32), persistent CTAs
    gemm_f16<false><<<HEADS * NSLOT, 128, GSMEM>>>(Yn_p, Wh_p, out, bias, nullptr);
}

// round 10
// speedup vs baseline: 2.1951x; 1.0929x over previous
#include <cuda_runtime.h>
#include <cuda_fp16.h>
#include <cstdint>

#define DIN 448
#define HEADS 8
#define HD 56
#define SEQ 8192
#define TOKENS 65536
#define NSLOT 37                      // CTAs per head; grid = 8*37 = 296 = 2/SM
#define MTILES 256                    // 65536 / 256

// ---------------- scratch (device globals; no runtime alloc) ---------------
__device__ __half Eh_g[DIN * DIN];
__device__ __half Wh_g[DIN * DIN];
__device__ __half Xh_g[(size_t)TOKENS * DIN];
__device__ __half Yn_g[(size_t)TOKENS * DIN];

// ---------------- helpers --------------------------------------------------
#define CP_ASYNC16(dst, src) \
    asm volatile("cp.async.cg.shared.global [%0], [%1], 16;" :: "r"(dst), "l"(src) : "memory")
#define CP_COMMIT() asm volatile("cp.async.commit_group;" ::: "memory")
#define CP_WAIT1()  asm volatile("cp.async.wait_group 1;" ::: "memory")
#define CP_WAIT0()  asm volatile("cp.async.wait_group 0;" ::: "memory")

__device__ __forceinline__ uint32_t smem_u32(const void* p) {
    uint32_t a;
    asm("{ .reg .u64 t; cvta.to.shared.u64 t, %1; cvt.u32.u64 %0, t; }"
        : "=r"(a) : "l"(p));
    return a;
}

// ---------------- persistent GEMM: C[M,448] = A[M,448]*B[448,448]^T --------
// CTA: one head (56 cols) x 6-7 M-tiles of 256 rows. 4 warps, warp tile 64x56
// (4 m16 x 7 n8), m16n8k16 HMMA, f32 acc. BK=64 (128B rows), SW128 swizzle,
// LDS.64 k-relabel. B (56x448) resident; A 2-stage cp.async, WARP-PRIVATE:
// warp w loads/reads only A rows [w*64, w*64+64) => mainloop needs only
// __syncwarp (no CTA barriers). 2 CTAs/SM.
// LN=true : register-only LayerNorm epilogue -> fp16 Yn (g1=gamma, g2=beta)
// LN=false: bias epilogue -> f32 out (g1=bias)
#define GBM 256
#define GBK 64
#define A_BYTES (GBM * 128)              // 32768 per stage
#define SB_OFF  (2 * A_BYTES)            // 65536
#define B_CHUNK (HD * 128)               // 7168 per k-tile
#define NKT     (DIN / GBK)              // 7
#define GSMEM   (SB_OFF + NKT * B_CHUNK) // 115712

template<bool LN>
__global__ __launch_bounds__(128, 2) void gemm_f16(
    const __half* __restrict__ Ag,
    const __half* __restrict__ Bg,
    void* __restrict__ Og,
    const float* __restrict__ g1,
    const float* __restrict__ g2)
{
    extern __shared__ char sm[];
    const uint32_t sb = smem_u32(sm);
    const int tid  = threadIdx.x;
    const int warp = tid >> 5, lane = tid & 31;
    const int g  = lane >> 2, li = lane & 3;
    const int hh   = blockIdx.x & 7;              // head (n-chunk)
    const int slot = blockIdx.x >> 3;             // 0..36
    const int N0 = hh * HD;
    const int ntile = (slot + NSLOT * 6 < MTILES) ? 7 : 6;
    const int total = ntile * NKT;

    uint32_t arow[4], brow[7], swk[4];
    #pragma unroll
    for (int mt = 0; mt < 4; mt++) arow[mt] = (uint32_t)((warp * 64 + mt * 16 + g) * 128);
    #pragma unroll
    for (int nt = 0; nt < 7; nt++) brow[nt] = (uint32_t)((nt * 8 + g) * 128);
    #pragma unroll
    for (int kk = 0; kk < 4; kk++)
        swk[kk] = (uint32_t)((((2 * kk + (li >> 1)) ^ g) << 4) | ((li & 1) << 3));

    // hoisted per-lane epilogue params
    float2 p1[7], p2[7];
    #pragma unroll
    for (int nt = 0; nt < 7; nt++) {
        if (LN) {
            const int c = g * 56 + nt * 8 + 2 * li;      // permuted channel
            p1[nt] = *(const float2*)&g1[c];
            p2[nt] = *(const float2*)&g2[c];
        } else {
            const int c = N0 + nt * 8 + 2 * li;          // plain channel
            p1[nt] = *(const float2*)&g1[c];
        }
    }

    // warp-private A loader: warp w fills rows [w*64, w*64+64) of stage st
    auto load_tileA = [&](int mi, int kt, int st) {
        const __half* asrc = Ag + ((size_t)mi * GBM + warp * 64) * DIN + (size_t)kt * GBK;
        const uint32_t ab = sb + st * A_BYTES + (uint32_t)warp * 64 * 128;
        #pragma unroll
        for (int j = 0; j < 16; j++) {            // 64 rows x 8 chunks / 32 lanes
            int id = lane + 32 * j, r = id >> 3, c = id & 7;
            CP_ASYNC16(ab + (uint32_t)r * 128 + ((uint32_t)((c ^ (r & 7)) << 4)),
                       asrc + (size_t)r * DIN + c * 8);
        }
    };

    // ---- prologue: whole B (cooperative) then warp-private A0, A1 ----
    #pragma unroll
    for (int j = 0; j < 25; j++) {                // 7*56*8 = 3136 16B ops
        int o = tid + 128 * j;
        if (o < NKT * HD * 8) {
            int kt = o / (HD * 8), rem = o % (HD * 8);
            int row = rem >> 3, c2 = rem & 7;
            CP_ASYNC16(sb + SB_OFF + kt * B_CHUNK + (uint32_t)row * 128
                           + ((uint32_t)((c2 ^ (row & 7)) << 4)),
                       Bg + (size_t)(N0 + row) * DIN + (size_t)kt * GBK + c2 * 8);
        }
    }
    load_tileA(slot, 0, 0); CP_COMMIT();          // group0 = B + A0
    load_tileA(slot, 1, 1); CP_COMMIT();          // group1 = A1

    float acc[4][7][4];
    #pragma unroll
    for (int mt = 0; mt < 4; mt++)
        #pragma unroll
        for (int nt = 0; nt < 7; nt++)
            #pragma unroll
            for (int r = 0; r < 4; r++) acc[mt][nt][r] = 0.f;

    int ck = 0, cmi = slot;        // consume coords
    int pk = 2, pmi = slot;        // prefetch coords (tile t+2)

    for (int t = 0; t < total; t++) {
        if (t < total - 1) { CP_WAIT1(); } else { CP_WAIT0(); }
        if (t == 0) __syncthreads();               // B panel visible to all warps
        else        __syncwarp();                  // warp-local A visibility
        const char* sa  = sm + (t & 1) * A_BYTES;
        const char* sbp = sm + SB_OFF + ck * B_CHUNK;

        #pragma unroll
        for (int kk = 0; kk < 4; kk++) {
            const uint32_t sw = swk[kk];
            uint2 a0[4], a1[4], bv[7];
            #pragma unroll
            for (int mt = 0; mt < 4; mt++) {
                a0[mt] = *(const uint2*)(sa + arow[mt] + sw);
                a1[mt] = *(const uint2*)(sa + arow[mt] + 1024 + sw);
            }
            #pragma unroll
            for (int nt = 0; nt < 7; nt++)
                bv[nt] = *(const uint2*)(sbp + brow[nt] + sw);
            #pragma unroll
            for (int mt = 0; mt < 4; mt++)
                #pragma unroll
                for (int nt = 0; nt < 7; nt++) {
                    asm volatile(
                        "mma.sync.aligned.m16n8k16.row.col.f32.f16.f16.f32 "
                        "{%0,%1,%2,%3}, {%4,%5,%6,%7}, {%8,%9}, {%0,%1,%2,%3};\n"
                        : "+f"(acc[mt][nt][0]), "+f"(acc[mt][nt][1]),
                          "+f"(acc[mt][nt][2]), "+f"(acc[mt][nt][3])
                        : "r"(a0[mt].x), "r"(a1[mt].x), "r"(a0[mt].y), "r"(a1[mt].y),
                          "r"(bv[nt].x), "r"(bv[nt].y));
                }
        }
        __syncwarp();                              // all lanes done reading stage t&1
        if (t + 2 < total) {
            load_tileA(pmi, pk, t & 1);
            CP_COMMIT();
            if (++pk == NKT) { pk = 0; pmi += NSLOT; }
        }

        if (ck == NKT - 1) {
            // ================= epilogue for m-tile cmi =====================
            const size_t M0 = (size_t)cmi * GBM;
            if (LN) {
                __half* Yn = (__half*)Og;
                #pragma unroll
                for (int mt = 0; mt < 4; mt++) {
                    const size_t tok0 = M0 + warp * 64 + mt * 16;
                    #pragma unroll
                    for (int hf = 0; hf < 2; hf++) {
                        const int lo = hf * 2;
                        float s = 0.f;
                        #pragma unroll
                        for (int nt = 0; nt < 7; nt++)
                            s += acc[mt][nt][lo] + acc[mt][nt][lo + 1];
                        #pragma unroll
                        for (int o = 16; o > 0; o >>= 1)
                            s += __shfl_xor_sync(0xffffffffu, s, o);
                        const float mu = s * (1.f / 448.f);
                        float vs = 0.f;
                        #pragma unroll
                        for (int nt = 0; nt < 7; nt++) {
                            float d0 = acc[mt][nt][lo] - mu;
                            float d1 = acc[mt][nt][lo + 1] - mu;
                            vs += d0 * d0 + d1 * d1;
                        }
                        #pragma unroll
                        for (int o = 16; o > 0; o >>= 1)
                            vs += __shfl_xor_sync(0xffffffffu, vs, o);
                        const float rsig = rsqrtf(vs * (1.f / 448.f) + 1e-5f);

                        const size_t tok = tok0 + hf * 8;
                        const size_t R = (tok >> 13) * SEQ + (size_t)hh * 1024
                                       + ((tok & 8191) >> 3);
                        __half* op = Yn + R * DIN + g * 56 + 2 * li;
                        #pragma unroll
                        for (int nt = 0; nt < 7; nt++) {
                            *(__half2*)(op + nt * 8) = __floats2half2_rn(
                                (acc[mt][nt][lo]     - mu) * rsig * p1[nt].x + p2[nt].x,
                                (acc[mt][nt][lo + 1] - mu) * rsig * p1[nt].y + p2[nt].y);
                        }
                    }
                }
            } else {
                float* Cg = (float*)Og;
                #pragma unroll
                for (int mt = 0; mt < 4; mt++) {
                    const size_t r0 = M0 + warp * 64 + mt * 16 + g;
                    #pragma unroll
                    for (int nt = 0; nt < 7; nt++) {
                        const int c0 = N0 + nt * 8 + 2 * li;
                        *(float2*)&Cg[r0 * DIN + c0] =
                            make_float2(acc[mt][nt][0] + p1[nt].x, acc[mt][nt][1] + p1[nt].y);
                        *(float2*)&Cg[(r0 + 8) * DIN + c0] =
                            make_float2(acc[mt][nt][2] + p1[nt].x, acc[mt][nt][3] + p1[nt].y);
                    }
                }
            }
            #pragma unroll
            for (int mt = 0; mt < 4; mt++)
                #pragma unroll
                for (int nt = 0; nt < 7; nt++)
                    #pragma unroll
                    for (int r = 0; r < 4; r++) acc[mt][nt][r] = 0.f;
            ck = 0; cmi += NSLOT;
        } else {
            ck++;
        }
    }
}

// ---------------- f32 -> fp16 conversion pass ------------------------------
__global__ void conv_h(const float4* __restrict__ src, __half2* __restrict__ dst, int n4) {
    int i = blockIdx.x * blockDim.x + threadIdx.x;
    if (i < n4) {
        float4 v = src[i];
        dst[2 * i]     = __floats2half2_rn(v.x, v.y);
        dst[2 * i + 1] = __floats2half2_rn(v.z, v.w);
    }
}

// ---------------- E_h = C_h * M^T * A_h^T * B_h  (-> fp16) -----------------
__global__ void computeE_k(const float* __restrict__ A, const float* __restrict__ B,
                           const float* __restrict__ C) {
    __shared__ float G[HD * HD], Cs[HD * HD], F[7 * HD];
    const int h = blockIdx.x, oc = blockIdx.y;
    const int tid = threadIdx.x;     // 448 threads
    for (int i = tid; i < HD * HD; i += 448) {
        G[i]  = A[h * HD * HD + i];
        Cs[i] = C[h * HD * HD + i];
    }
    __syncthreads();
    if (tid < HD) {
        #pragma unroll
        for (int e = HD - 2; e >= 0; e--) G[tid * HD + e] += G[tid * HD + e + 1];
    }
    __syncthreads();
    if (tid < 7 * HD) {
        int ol = tid / HD, d = tid % HD;
        float s = 0.f;
        #pragma unroll
        for (int e = 0; e < HD; e++) s += Cs[(oc * 7 + ol) * HD + e] * G[d * HD + e];
        F[ol * HD + d] = s;
    }
    __syncthreads();
    const int i = tid;
    float acc[7] = {0, 0, 0, 0, 0, 0, 0};
    for (int d = 0; d < HD; d++) {
        float b = B[(size_t)(h * HD + d) * DIN + i];
        #pragma unroll
        for (int ol = 0; ol < 7; ol++) acc[ol] += F[ol * HD + d] * b;
    }
    #pragma unroll
    for (int ol = 0; ol < 7; ol++)
        Eh_g[(size_t)(h * HD + oc * 7 + ol) * DIN + i] = __float2half_rn(acc[ol]);
}

// ---------------------------------------------------------------------------
extern "C" void kernel_launch(void* const* d_in, const int* in_sizes, int n_in,
                              void* d_out, int out_size) {
    const float* x     = (const float*)d_in[0];
    const float* A     = (const float*)d_in[1];
    const float* B     = (const float*)d_in[2];
    const float* C     = (const float*)d_in[3];
    const float* gamma = (const float*)d_in[4];
    const float* beta  = (const float*)d_in[5];
    const float* W     = (const float*)d_in[6];
    const float* bias  = (const float*)d_in[7];
    float* out = (float*)d_out;

    __half *Eh_p, *Wh_p, *Xh_p, *Yn_p;
    cudaGetSymbolAddress((void**)&Eh_p, Eh_g);
    cudaGetSymbolAddress((void**)&Wh_p, Wh_g);
    cudaGetSymbolAddress((void**)&Xh_p, Xh_g);
    cudaGetSymbolAddress((void**)&Yn_p, Yn_g);

    cudaFuncSetAttribute(gemm_f16<true>,
                         cudaFuncAttributeMaxDynamicSharedMemorySize, GSMEM);
    cudaFuncSetAttribute(gemm_f16<false>,
                         cudaFuncAttributeMaxDynamicSharedMemorySize, GSMEM);

    conv_h<<<28672, 256>>>((const float4*)x, (__half2*)Xh_p, 7340032);
    conv_h<<<196,   256>>>((const float4*)W, (__half2*)Wh_p, 50176);
    computeE_k<<<dim3(HEADS, 8), DIN>>>(A, B, C);

    // GEMM1 + LayerNorm + permutation fused -> Yn (fp16), persistent CTAs
    gemm_f16<true><<<HEADS * NSLOT, 128, GSMEM>>>(Xh_p, Eh_p, Yn_p, gamma, beta);
    // GEMM2 + bias -> out (f32), persistent CTAs
    gemm_f16<false><<<HEADS * NSLOT, 128, GSMEM>>>(Yn_p, Wh_p, out, bias, nullptr);
}

// round 12
// speedup vs baseline: 2.2427x; 1.0217x over previous
#include <cuda_runtime.h>
#include <cuda_fp16.h>
#include <cstdint>

#define DIN 448
#define HEADS 8
#define HD 56
#define SEQ 8192
#define TOKENS 65536
#define NSLOT 37                      // CTAs per head; grid = 8*37 = 296 = 2/SM
#define MTILES 256                    // 65536 / 256
#define NKT    7                      // 448 / 64
#define GBK    64                     // k-tile depth (halves)

// ---------------- scratch (device globals; no runtime alloc) ---------------
// A-side matrices live in FRAGMENT-BLOB layout (see blob mapping below).
__device__ __half Eh_g[DIN * DIN];
__device__ __half Wh_g[DIN * DIN];
__device__ uint4  Xb_g[(size_t)TOKENS * DIN / 8];   // x  blob (fp16)
__device__ uint4  Yb_g[(size_t)TOKENS * DIN / 8];   // Yn blob (fp16)

// Blob mapping for a [rows, 448] fp16 matrix:
//   row: mi=row>>8, rt=row&255, w=rt>>6, mt=(rt>>4)&3, hi=(rt>>3)&1, g=rt&7
//   col: kt=col>>6, kk=(col>>4)&3, li=(col>>2)&3, p=col&3
//   uint4 index = ((mi*7+kt)*16 + w*4 + kk)*128 + mt*32 + g*4 + li
//   16B unit = {(row g, p01), (row g+8, p01), (row g, p23), (row g+8, p23)}
//   = MMA regs {a0,a1,a2,a3} under the phys-col relabel
//   hw{2li,2li+1}->4li,4li+1 ; hw{2li+8,2li+9}->4li+2,4li+3
//   (same relabel applied to B fragments -> contraction exact).

// ---------------- helpers --------------------------------------------------
#define CP_ASYNC16(dst, src) \
    asm volatile("cp.async.cg.shared.global [%0], [%1], 16;" :: "r"(dst), "l"(src) : "memory")
#define CP_COMMIT() asm volatile("cp.async.commit_group;" ::: "memory")
#define CP_WAIT0()  asm volatile("cp.async.wait_group 0;" ::: "memory")

__device__ __forceinline__ uint32_t smem_u32(const void* p) {
    uint32_t a;
    asm("{ .reg .u64 t; cvta.to.shared.u64 t, %1; cvt.u32.u64 %0, t; }"
        : "=r"(a) : "l"(p));
    return a;
}

// ---------------- persistent GEMM: C[M,448] = A[M,448]*B[448,448]^T --------
// A in fragment blob (gmem, LDG.128 direct to MMA regs — NO smem for A).
// B (56x448 fp16, one head) resident in smem, SW128. 4 warps, warp tile
// 64x56, m16n8k16, f32 acc. Prefetch ring depth 4 (slot = kk). Barrier-free
// mainloop. 2 CTAs/SM.
// LN=true : LayerNorm epilogue -> Yn fragment blob (g1=gamma, g2=beta)
// LN=false: bias epilogue -> f32 linear out (g1=bias)
#define B_CHUNK (HD * 128)               // 7168 per k-tile
#define GSMEM   (NKT * B_CHUNK)          // 50176

template<bool LN>
__global__ __launch_bounds__(128, 2) void gemm_f16(
    const uint4* __restrict__ Ab,    // fragment blob
    const __half* __restrict__ Bg,   // [448,448] row-major [n,k]
    void* __restrict__ Og,
    const float* __restrict__ g1,
    const float* __restrict__ g2)
{
    extern __shared__ char sm[];
    const uint32_t sb = smem_u32(sm);
    const int tid  = threadIdx.x;
    const int warp = tid >> 5, lane = tid & 31;
    const int g  = lane >> 2, li = lane & 3;
    const int hh   = blockIdx.x & 7;
    const int slot = blockIdx.x >> 3;
    const int N0 = hh * HD;
    const int ntile = (slot + NSLOT * 6 < MTILES) ? 7 : 6;

    uint32_t brow[7], swk[4];
    #pragma unroll
    for (int nt = 0; nt < 7; nt++) brow[nt] = (uint32_t)((nt * 8 + g) * 128);
    #pragma unroll
    for (int kk = 0; kk < 4; kk++)
        swk[kk] = (uint32_t)((((2 * kk + (li >> 1)) ^ g) << 4) | ((li & 1) << 3));

    // ---- B panel -> smem (once) ----
    #pragma unroll
    for (int j = 0; j < 25; j++) {
        int o = tid + 128 * j;
        if (o < NKT * HD * 8) {
            int kt = o / (HD * 8), rem = o % (HD * 8);
            int row = rem >> 3, c2 = rem & 7;
            CP_ASYNC16(sb + kt * B_CHUNK + (uint32_t)row * 128
                           + ((uint32_t)((c2 ^ (row & 7)) << 4)),
                       Bg + (size_t)(N0 + row) * DIN + (size_t)kt * GBK + c2 * 8);
        }
    }
    CP_COMMIT();

    // ---- prologue: prefetch first k-tile's A fragments (ring slot = kk) ----
    uint4 frag[4][4];
    {
        const uint4* ap = Ab + ((size_t)(slot * 7 + 0) * 16 + warp * 4) * 128 + lane;
        #pragma unroll
        for (int kk = 0; kk < 4; kk++)
            #pragma unroll
            for (int mt = 0; mt < 4; mt++)
                frag[kk][mt] = ap[kk * 128 + mt * 32];
    }

    CP_WAIT0();
    __syncthreads();                      // B visible; only barrier in kernel

    float acc[4][7][4];
    #pragma unroll
    for (int mt = 0; mt < 4; mt++)
        #pragma unroll
        for (int nt = 0; nt < 7; nt++)
            #pragma unroll
            for (int r = 0; r < 4; r++) acc[mt][nt][r] = 0.f;

    int mi = slot;
    for (int ti = 0; ti < ntile; ti++) {
        for (int kt = 0; kt < NKT; kt++) {
            const char* sbp = sm + kt * B_CHUNK;
            const bool more = (kt < NKT - 1) || (ti < ntile - 1);
            const int nmi = (kt < NKT - 1) ? mi : mi + NSLOT;
            const int nkt = (kt < NKT - 1) ? kt + 1 : 0;
            const uint4* anx = Ab + ((size_t)(nmi * 7 + nkt) * 16 + warp * 4) * 128 + lane;

            #pragma unroll
            for (int kk = 0; kk < 4; kk++) {
                const uint32_t sw = swk[kk];
                uint2 bv[7];
                #pragma unroll
                for (int nt = 0; nt < 7; nt++)
                    bv[nt] = *(const uint2*)(sbp + brow[nt] + sw);
                #pragma unroll
                for (int mt = 0; mt < 4; mt++) {
                    const uint4 a = frag[kk][mt];
                    #pragma unroll
                    for (int nt = 0; nt < 7; nt++) {
                        asm volatile(
                            "mma.sync.aligned.m16n8k16.row.col.f32.f16.f16.f32 "
                            "{%0,%1,%2,%3}, {%4,%5,%6,%7}, {%8,%9}, {%0,%1,%2,%3};\n"
                            : "+f"(acc[mt][nt][0]), "+f"(acc[mt][nt][1]),
                              "+f"(acc[mt][nt][2]), "+f"(acc[mt][nt][3])
                            : "r"(a.x), "r"(a.y), "r"(a.z), "r"(a.w),
                              "r"(bv[nt].x), "r"(bv[nt].y));
                    }
                }
                if (more) {
                    #pragma unroll
                    for (int mt = 0; mt < 4; mt++)
                        frag[kk][mt] = anx[kk * 128 + mt * 32];
                }
            }
        }

        // ================= epilogue for m-tile mi ==========================
        if (LN) {
            // LayerNorm over permuted rows; write Yn fragment blob
            #pragma unroll
            for (int mt = 0; mt < 4; mt++) {
                const size_t tok0 = (size_t)mi * 256 + warp * 64 + mt * 16;
                #pragma unroll
                for (int hf = 0; hf < 2; hf++) {
                    const int lo = hf * 2;
                    float s = 0.f;
                    #pragma unroll
                    for (int nt = 0; nt < 7; nt++)
                        s += acc[mt][nt][lo] + acc[mt][nt][lo + 1];
                    #pragma unroll
                    for (int o = 16; o > 0; o >>= 1)
                        s += __shfl_xor_sync(0xffffffffu, s, o);
                    const float mu = s * (1.f / 448.f);
                    float vs = 0.f;
                    #pragma unroll
                    for (int nt = 0; nt < 7; nt++) {
                        float d0 = acc[mt][nt][lo] - mu;
                        float d1 = acc[mt][nt][lo + 1] - mu;
                        vs += d0 * d0 + d1 * d1;
                    }
                    #pragma unroll
                    for (int o = 16; o > 0; o >>= 1)
                        vs += __shfl_xor_sync(0xffffffffu, vs, o);
                    const float rsig = rsqrtf(vs * (1.f / 448.f) + 1e-5f);

                    const size_t tok = tok0 + hf * 8;
                    const size_t R = (tok >> 13) * SEQ + (size_t)hh * 1024
                                   + ((tok & 8191) >> 3);
                    // blob address parts for output row R (byte offsets)
                    const uint32_t mi_o = (uint32_t)(R >> 8), rt = (uint32_t)R & 255;
                    const uint32_t rpart = mi_o * 229376u          // mi*7*16*128*16
                                         + (rt >> 6) * 8192u       // w_o*4*128*16
                                         + (((rt >> 4) & 3) * 512u)// mt_o*32*16
                                         + ((rt & 7) * 64u)        // g_o*4*16
                                         + (((rt >> 3) & 1) * 4u); // hi_o -> .y/.w half
                    char* yb = (char*)Og;
                    #pragma unroll
                    for (int nt = 0; nt < 7; nt++) {
                        const int c = g * 56 + nt * 8 + 2 * li;    // even channel
                        const uint32_t cpart = (uint32_t)(c >> 6) * 32768u   // kt_o*16*128*16
                                             + (uint32_t)((c >> 4) & 3) * 2048u // kk_o*128*16
                                             + (uint32_t)((c >> 2) & 3) * 16u   // li_o
                                             + (uint32_t)((c & 2) << 2);        // p-pair -> +8
                        *(__half2*)(yb + rpart + cpart) = __floats2half2_rn(
                            (acc[mt][nt][lo]     - mu) * rsig * g1[c]     + g2[c],
                            (acc[mt][nt][lo + 1] - mu) * rsig * g1[c + 1] + g2[c + 1]);
                    }
                }
            }
        } else {
            float* Cg = (float*)Og;
            #pragma unroll
            for (int mt = 0; mt < 4; mt++) {
                const size_t r0 = (size_t)mi * 256 + warp * 64 + mt * 16 + g;
                #pragma unroll
                for (int nt = 0; nt < 7; nt++) {
                    const int c0 = N0 + nt * 8 + 2 * li;
                    const float2 bb = *(const float2*)&g1[c0];
                    *(float2*)&Cg[r0 * DIN + c0] =
                        make_float2(acc[mt][nt][0] + bb.x, acc[mt][nt][1] + bb.y);
                    *(float2*)&Cg[(r0 + 8) * DIN + c0] =
                        make_float2(acc[mt][nt][2] + bb.x, acc[mt][nt][3] + bb.y);
                }
            }
        }
        #pragma unroll
        for (int mt = 0; mt < 4; mt++)
            #pragma unroll
            for (int nt = 0; nt < 7; nt++)
                #pragma unroll
                for (int r = 0; r < 4; r++) acc[mt][nt][r] = 0.f;
        mi += NSLOT;
    }
}

// ---------------- x (f32) -> fragment blob (fp16) --------------------------
// One thread per 16B blob unit; unit id == blob uint4 index (coalesced STG).
__global__ void conv_blob(const float* __restrict__ X, uint4* __restrict__ Out,
                          int nunits) {
    int id = blockIdx.x * blockDim.x + threadIdx.x;
    if (id >= nunits) return;
    const int lane = id & 31, li = lane & 3, gg = lane >> 2;
    const int mt = (id >> 5) & 3, kk = (id >> 7) & 3, w = (id >> 9) & 3;
    const int ktmi = id >> 11;
    const int mi = ktmi / 7, kt = ktmi - mi * 7;
    const int r0 = mi * 256 + w * 64 + mt * 16 + gg;
    const int c0 = kt * 64 + kk * 16 + li * 4;
    const float4 v0 = *(const float4*)(X + (size_t)r0 * DIN + c0);
    const float4 v1 = *(const float4*)(X + (size_t)(r0 + 8) * DIN + c0);
    __half2 h0 = __floats2half2_rn(v0.x, v0.y);   // row g,   p01
    __half2 h1 = __floats2half2_rn(v1.x, v1.y);   // row g+8, p01
    __half2 h2 = __floats2half2_rn(v0.z, v0.w);   // row g,   p23
    __half2 h3 = __floats2half2_rn(v1.z, v1.w);   // row g+8, p23
    uint4 o;
    o.x = *(uint32_t*)&h0; o.y = *(uint32_t*)&h1;
    o.z = *(uint32_t*)&h2; o.w = *(uint32_t*)&h3;
    Out[id] = o;
}

// ---------------- f32 -> fp16 linear conversion (for W) --------------------
__global__ void conv_h(const float4* __restrict__ src, __half2* __restrict__ dst, int n4) {
    int i = blockIdx.x * blockDim.x + threadIdx.x;
    if (i < n4) {
        float4 v = src[i];
        dst[2 * i]     = __floats2half2_rn(v.x, v.y);
        dst[2 * i + 1] = __floats2half2_rn(v.z, v.w);
    }
}

// ---------------- E_h = C_h * M^T * A_h^T * B_h  (-> fp16) -----------------
__global__ void computeE_k(const float* __restrict__ A, const float* __restrict__ B,
                           const float* __restrict__ C) {
    __shared__ float G[HD * HD], Cs[HD * HD], F[7 * HD];
    const int h = blockIdx.x, oc = blockIdx.y;
    const int tid = threadIdx.x;     // 448 threads
    for (int i = tid; i < HD * HD; i += 448) {
        G[i]  = A[h * HD * HD + i];
        Cs[i] = C[h * HD * HD + i];
    }
    __syncthreads();
    if (tid < HD) {
        #pragma unroll
        for (int e = HD - 2; e >= 0; e--) G[tid * HD + e] += G[tid * HD + e + 1];
    }
    __syncthreads();
    if (tid < 7 * HD) {
        int ol = tid / HD, d = tid % HD;
        float s = 0.f;
        #pragma unroll
        for (int e = 0; e < HD; e++) s += Cs[(oc * 7 + ol) * HD + e] * G[d * HD + e];
        F[ol * HD + d] = s;
    }
    __syncthreads();
    const int i = tid;
    float acc[7] = {0, 0, 0, 0, 0, 0, 0};
    for (int d = 0; d < HD; d++) {
        float b = B[(size_t)(h * HD + d) * DIN + i];
        #pragma unroll
        for (int ol = 0; ol < 7; ol++) acc[ol] += F[ol * HD + d] * b;
    }
    #pragma unroll
    for (int ol = 0; ol < 7; ol++)
        Eh_g[(size_t)(h * HD + oc * 7 + ol) * DIN + i] = __float2half_rn(acc[ol]);
}

// ---------------------------------------------------------------------------
extern "C" void kernel_launch(void* const* d_in, const int* in_sizes, int n_in,
                              void* d_out, int out_size) {
    const float* x     = (const float*)d_in[0];
    const float* A     = (const float*)d_in[1];
    const float* B     = (const float*)d_in[2];
    const float* C     = (const float*)d_in[3];
    const float* gamma = (const float*)d_in[4];
    const float* beta  = (const float*)d_in[5];
    const float* W     = (const float*)d_in[6];
    const float* bias  = (const float*)d_in[7];
    float* out = (float*)d_out;

    __half *Eh_p, *Wh_p;
    uint4 *Xb_p, *Yb_p;
    cudaGetSymbolAddress((void**)&Eh_p, Eh_g);
    cudaGetSymbolAddress((void**)&Wh_p, Wh_g);
    cudaGetSymbolAddress((void**)&Xb_p, Xb_g);
    cudaGetSymbolAddress((void**)&Yb_p, Yb_g);

    cudaFuncSetAttribute(gemm_f16<true>,
                         cudaFuncAttributeMaxDynamicSharedMemorySize, GSMEM);
    cudaFuncSetAttribute(gemm_f16<false>,
                         cudaFuncAttributeMaxDynamicSharedMemorySize, GSMEM);

    const int nunits = TOKENS * DIN / 8;          // 3,670,016
    conv_blob<<<nunits / 256, 256>>>(x, Xb_p, nunits);
    conv_h<<<196, 256>>>((const float4*)W, (__half2*)Wh_p, 50176);
    computeE_k<<<dim3(HEADS, 8), DIN>>>(A, B, C);

    // GEMM1 (+LN, permuted) : x-blob @ E^T -> Yn blob
    gemm_f16<true><<<HEADS * NSLOT, 128, GSMEM>>>(Xb_p, Eh_p, Yb_p, gamma, beta);
    // GEMM2 (+bias)         : Yn-blob @ W^T -> out (f32 linear)
    gemm_f16<false><<<HEADS * NSLOT, 128, GSMEM>>>(Yb_p, Wh_p, out, bias, nullptr);
}